// round 14
// baseline (speedup 1.0000x reference)
#include <cuda_runtime.h>
#include <cuda_bf16.h>
#include <math.h>
#include <stdint.h>

// Problem constants
#define NB   8192
#define NC   200
#define NK   16
#define ND   512
#define NCK  3200
#define K2   1024          // 2*ND concatenated GEMM K
#define D_LOG_2PI 940.9930579935848f

// GEMM tiling (champion config)
#define BM 128
#define BN 128
#define BK 32
#define NSTEPS (K2/BK)     // 32
#define NTHR 256
#define NSTAGE 3

#define STAGE_BYTES 32768
#define BIAS_OFF    (NSTAGE * STAGE_BYTES)          // bias AFTER stages
#define SMEM_TOTAL  (BIAS_OFF + 512)
#define CPAD 136

// fused prep grid partition
#define PX_BLOCKS 4096                  // NB*ND/4/256
#define PC_BLOCKS NCK                   // one component per block
#define PREP_BLOCKS (PX_BLOCKS + PC_BLOCKS + 1)

// ---------------- scratch (device globals) ----------------
__device__ __nv_bfloat16 g_Ah[NB * K2];
__device__ __nv_bfloat16 g_Al[NB * K2];
__device__ __nv_bfloat16 g_Bh[NCK * K2];
__device__ __nv_bfloat16 g_Bl[NCK * K2];
__device__ float g_bias[NCK];
__device__ float g_logp[NC];
__device__ float g_cls[NB * NC];

// ---------------- helpers ----------------
__device__ __forceinline__ uint32_t smem_u32(const void* p) {
    uint32_t a;
    asm("{ .reg .u64 t; cvta.to.shared.u64 t, %1; cvt.u32.u64 %0, t; }" : "=r"(a) : "l"(p));
    return a;
}
__device__ __forceinline__ uint32_t swz(uint32_t o) {   // SW128 over 128B rows
    return o ^ (((o >> 7) & 7) << 4);
}
__device__ __forceinline__ void cp16(uint32_t saddr, const void* gaddr) {
    asm volatile("cp.async.cg.shared.global [%0], [%1], 16;" :: "r"(saddr), "l"(gaddr));
}
__device__ __forceinline__ void ldsm4(uint32_t* r, uint32_t addr) {
    asm volatile("ldmatrix.sync.aligned.m8n8.x4.shared.b16 {%0,%1,%2,%3}, [%4];"
        : "=r"(r[0]), "=r"(r[1]), "=r"(r[2]), "=r"(r[3]) : "r"(addr));
}
__device__ __forceinline__ void mma4(float* c, const uint32_t* a, uint32_t b0, uint32_t b1) {
    asm("mma.sync.aligned.m16n8k16.row.col.f32.bf16.bf16.f32 "
        "{%0,%1,%2,%3}, {%4,%5,%6,%7}, {%8,%9}, {%0,%1,%2,%3};"
        : "+f"(c[0]), "+f"(c[1]), "+f"(c[2]), "+f"(c[3])
        : "r"(a[0]), "r"(a[1]), "r"(a[2]), "r"(a[3]), "r"(b0), "r"(b1));
}
__device__ __forceinline__ uint32_t pack2(__nv_bfloat16 a, __nv_bfloat16 b) {
    __nv_bfloat162 v(a, b);
    return *(uint32_t*)&v;
}

// ================= fused prep: x-split | comp-split+bias | priors =================
__global__ void fused_prep_kernel(const float* __restrict__ x,
                                  const float* __restrict__ means,
                                  const float* __restrict__ bw,
                                  const float* __restrict__ weights,
                                  const float* __restrict__ priors) {
    __shared__ float sh[256];
    int bid = blockIdx.x;
    int t = threadIdx.x;

    if (bid < PX_BLOCKS) {
        // ---- A' = [x^2 | x] hi/lo, 4 elems/thread, 8B packed stores ----
        int i = bid * 256 + t;          // over NB*ND/4, exact
        int b = i >> 7;
        int d4 = (i & 127) * 4;
        float4 v = *(const float4*)(x + (size_t)b * ND + d4);
        float vv[4] = {v.x, v.y, v.z, v.w};
        __nv_bfloat16 h[4], l[4], h2[4], l2[4];
        #pragma unroll
        for (int q = 0; q < 4; q++) {
            float a = vv[q] * vv[q];
            h[q] = __float2bfloat16(a);
            l[q] = __float2bfloat16(a - __bfloat162float(h[q]));
            h2[q] = __float2bfloat16(vv[q]);
            l2[q] = __float2bfloat16(vv[q] - __bfloat162float(h2[q]));
        }
        size_t base = (size_t)b * K2 + d4;
        *(uint2*)(g_Ah + base)      = make_uint2(pack2(h[0], h[1]),  pack2(h[2], h[3]));
        *(uint2*)(g_Al + base)      = make_uint2(pack2(l[0], l[1]),  pack2(l[2], l[3]));
        *(uint2*)(g_Ah + base + ND) = make_uint2(pack2(h2[0], h2[1]), pack2(h2[2], h2[3]));
        *(uint2*)(g_Al + base + ND) = make_uint2(pack2(l2[0], l2[1]), pack2(l2[2], l2[3]));

    } else if (bid < PX_BLOCKS + PC_BLOCKS) {
        // ---- B' = [invb | -2mu*invb] hi/lo + bias(j), 2 elems/thread ----
        int j = bid - PX_BLOCKS;
        int d2 = t * 2;
        float2 bv2 = *(const float2*)(bw + (size_t)j * ND + d2);
        float2 mu2 = *(const float2*)(means + (size_t)j * ND + d2);
        float bvv[2] = {bv2.x, bv2.y};
        float muv[2] = {mu2.x, mu2.y};
        float ld = 0.f, cj = 0.f;
        __nv_bfloat16 bh[2], bl[2], mh[2], ml[2];
        #pragma unroll
        for (int q = 0; q < 2; q++) {
            float bv = fminf(fmaxf(bvv[q], 1e-6f), 1000.f);
            float inv = 1.0f / bv;
            float m2  = -2.0f * muv[q] * inv;
            bh[q] = __float2bfloat16(inv);
            bl[q] = __float2bfloat16(inv - __bfloat162float(bh[q]));
            mh[q] = __float2bfloat16(m2);
            ml[q] = __float2bfloat16(m2 - __bfloat162float(mh[q]));
            ld += logf(bv);
            cj += muv[q] * muv[q] * inv;
        }
        size_t base = (size_t)j * K2 + d2;
        *(uint32_t*)(g_Bh + base)      = pack2(bh[0], bh[1]);
        *(uint32_t*)(g_Bl + base)      = pack2(bl[0], bl[1]);
        *(uint32_t*)(g_Bh + base + ND) = pack2(mh[0], mh[1]);
        *(uint32_t*)(g_Bl + base + ND) = pack2(ml[0], ml[1]);

        // reduce ld, cj over 256 threads
        #pragma unroll
        for (int o = 16; o > 0; o >>= 1) {
            ld += __shfl_down_sync(0xffffffff, ld, o);
            cj += __shfl_down_sync(0xffffffff, cj, o);
        }
        if ((t & 31) == 0) { sh[t >> 5] = ld; sh[8 + (t >> 5)] = cj; }
        __syncthreads();
        if (t == 0) {
            float LD = 0.f, CJ = 0.f;
            #pragma unroll
            for (int w = 0; w < 8; w++) { LD += sh[w]; CJ += sh[8 + w]; }
            // local class-weight softmax -> logw_j (no cross-block dependency)
            int c = j >> 4, k = j & 15;
            float wv[NK];
            float m = -1e30f;
            #pragma unroll
            for (int q = 0; q < NK; q++) { wv[q] = weights[c * NK + q]; m = fmaxf(m, wv[q]); }
            float s = 0.f;
            #pragma unroll
            for (int q = 0; q < NK; q++) s += expf(wv[q] - m);
            float logw = logf(expf(wv[k] - m) / s + 1e-6f);
            g_bias[j] = -0.5f * (D_LOG_2PI + LD + CJ) + logw;
        }

    } else {
        // ---- priors softmax -> g_logp ----
        float pv = (t < NC) ? priors[t] : -1e30f;
        sh[t] = pv;
        __syncthreads();
        for (int s = 128; s > 0; s >>= 1) { if (t < s) sh[t] = fmaxf(sh[t], sh[t + s]); __syncthreads(); }
        float M = sh[0];
        __syncthreads();
        float e = (t < NC) ? expf(pv - M) : 0.f;
        sh[t] = e;
        __syncthreads();
        for (int s = 128; s > 0; s >>= 1) { if (t < s) sh[t] += sh[t + s]; __syncthreads(); }
        float S = sh[0];
        if (t < NC) g_logp[t] = logf(e / S + 1e-6f);
    }
}

// ---------------- main GEMM (champion, bf16x3, 2 CTAs/SM) ----------------
__global__ void __launch_bounds__(NTHR, 2) gemm_kernel() {
    extern __shared__ char smem[];
    uint32_t sb = smem_u32(smem);
    int tid = threadIdx.x;
    int wid = tid >> 5, lane = tid & 31;
    int rowBase = blockIdx.y * BM;
    int colBase = blockIdx.x * BN;
    float* bias_sm = (float*)(smem + BIAS_OFF);

    if (tid < 128) bias_sm[tid] = g_bias[colBase + tid];

    int wm = (wid & 1) * 64;
    int wn = (wid >> 1) * 32;
    int lrow = lane & 15;
    uint32_t lcol = (uint32_t)((lane >> 4) * 16);

    const __nv_bfloat16* pA[4]; uint32_t sA[4];
    const __nv_bfloat16* pB[4]; uint32_t sB[4];
    #pragma unroll
    for (int it = 0; it < 4; it++) {
        int idx = tid + it * NTHR;
        int row = idx >> 3, ch = idx & 7;
        uint32_t goff = (uint32_t)((rowBase + row) * K2 + (ch & 3) * 8);
        pA[it] = (ch < 4 ? g_Ah : g_Al) + goff;
        sA[it] = swz((uint32_t)(row * 128 + ch * 16));
        uint32_t goffB = (uint32_t)((colBase + row) * K2 + (ch & 3) * 8);
        pB[it] = (ch < 4 ? g_Bh : g_Bl) + goffB;
        sB[it] = swz((uint32_t)(row * 128 + ch * 16));
    }

    uint32_t baseA[4], baseB[2];
    #pragma unroll
    for (int mi = 0; mi < 4; mi++) {
        int r = wm + mi * 16 + lrow;
        baseA[mi] = sb + (uint32_t)(r * 128 + ((r & 7) << 4));
    }
    #pragma unroll
    for (int nj = 0; nj < 2; nj++) {
        int r = wn + nj * 16 + lrow;
        baseB[nj] = sb + 16384 + (uint32_t)(r * 128 + ((r & 7) << 4));
    }

    float acc[64];
    #pragma unroll
    for (int i = 0; i < 64; i++) acc[i] = 0.f;

    auto load_stage = [&](int st) {
        uint32_t sa = sb + (uint32_t)st * STAGE_BYTES;
        #pragma unroll
        for (int it = 0; it < 4; it++) {
            cp16(sa + sA[it],          pA[it]);
            cp16(sa + 16384 + sB[it],  pB[it]);
            pA[it] += BK;
            pB[it] += BK;
        }
        asm volatile("cp.async.commit_group;" ::: "memory");
    };

    load_stage(0);
    load_stage(1);

    int st = 0;
    for (int s = 0; s < NSTEPS; s++) {
        if (s < NSTEPS - 2)
            asm volatile("cp.async.wait_group 1;" ::: "memory");
        else
            asm volatile("cp.async.wait_group 0;" ::: "memory");
        __syncthreads();

        uint32_t so = (uint32_t)st * STAGE_BYTES;

        if (s + 2 < NSTEPS) {
            int nst = st + 2; if (nst >= NSTAGE) nst -= NSTAGE;
            load_stage(nst);
        }

        #pragma unroll
        for (int ks = 0; ks < 2; ks++) {
            uint32_t kb = (uint32_t)(ks * 32) + lcol;
            uint32_t kl = kb + 64u;

            uint32_t bh0[4], bh1[4], bl0[4], bl1[4];
            ldsm4(bh0, (baseB[0] + so) ^ kb);
            ldsm4(bh1, (baseB[1] + so) ^ kb);
            ldsm4(bl0, (baseB[0] + so) ^ kl);
            ldsm4(bl1, (baseB[1] + so) ^ kl);

            #pragma unroll
            for (int mi = 0; mi < 4; mi++) {
                float* C = &acc[mi * 16];
                uint32_t ah[4], al[4];
                ldsm4(ah, (baseA[mi] + so) ^ kb);
                mma4(C + 0,  ah, bh0[0], bh0[2]);
                mma4(C + 4,  ah, bh0[1], bh0[3]);
                mma4(C + 8,  ah, bh1[0], bh1[2]);
                mma4(C + 12, ah, bh1[1], bh1[3]);
                ldsm4(al, (baseA[mi] + so) ^ kl);
                mma4(C + 0,  ah, bl0[0], bl0[2]);
                mma4(C + 4,  ah, bl0[1], bl0[3]);
                mma4(C + 8,  ah, bl1[0], bl1[2]);
                mma4(C + 12, ah, bl1[1], bl1[3]);
                mma4(C + 0,  al, bh0[0], bh0[2]);
                mma4(C + 4,  al, bh0[1], bh0[3]);
                mma4(C + 8,  al, bh1[0], bh1[2]);
                mma4(C + 12, al, bh1[1], bh1[3]);
            }
        }
        st++; if (st >= NSTAGE) st = 0;
    }
    __syncthreads();

    // ---- epilogue: stage C to smem (offset 0; bias untouched), fused lse ----
    float* csh = (float*)smem;
    #pragma unroll
    for (int mi = 0; mi < 4; mi++)
        #pragma unroll
        for (int nj = 0; nj < 4; nj++) {
            float* a = &acc[(mi * 4 + nj) * 4];
            int r0 = wm + mi * 16 + (lane >> 2);
            int c0 = wn + nj * 8 + 2 * (lane & 3);
            csh[r0 * CPAD + c0]           = a[0];
            csh[r0 * CPAD + c0 + 1]       = a[1];
            csh[(r0 + 8) * CPAD + c0]     = a[2];
            csh[(r0 + 8) * CPAD + c0 + 1] = a[3];
        }
    __syncthreads();

    #pragma unroll
    for (int i = 0; i < 4; i++) {
        int p = tid + i * NTHR;
        int row = p >> 3, cl = p & 7;
        const float* base = &csh[row * CPAD + cl * 16];
        float4 x0 = *(const float4*)(base + 0);
        float4 x1 = *(const float4*)(base + 4);
        float4 x2 = *(const float4*)(base + 8);
        float4 x3 = *(const float4*)(base + 12);
        float v[16] = {x0.x, x0.y, x0.z, x0.w, x1.x, x1.y, x1.z, x1.w,
                       x2.x, x2.y, x2.z, x2.w, x3.x, x3.y, x3.z, x3.w};
        #pragma unroll
        for (int j = 0; j < 16; j++)
            v[j] = fmaf(-0.5f, v[j], bias_sm[cl * 16 + j]);
        float m = v[0];
        #pragma unroll
        for (int j = 1; j < 16; j++) m = fmaxf(m, v[j]);
        float sum = 0.f;
        #pragma unroll
        for (int j = 0; j < 16; j++) sum += __expf(v[j] - m);
        g_cls[(size_t)(rowBase + row) * NC + (colBase >> 4) + cl] = m + __logf(sum);
    }
}

// ---------------- per-row reduction over classes ----------------
__global__ void reduce_kernel(float* __restrict__ out) {
    __shared__ float sh[256];
    size_t row = blockIdx.x;
    int t = threadIdx.x;
    float lc = -1e30f;
    if (t < NC) lc = g_cls[row * NC + t] + g_logp[t];
    sh[t] = lc;
    __syncthreads();
    for (int s = 128; s > 0; s >>= 1) { if (t < s) sh[t] = fmaxf(sh[t], sh[t + s]); __syncthreads(); }
    float M = sh[0];
    __syncthreads();
    sh[t] = (t < NC) ? __expf(lc - M) : 0.f;
    __syncthreads();
    for (int s = 128; s > 0; s >>= 1) { if (t < s) sh[t] += sh[t + s]; __syncthreads(); }
    float lse = M + __logf(sh[0]);
    if (t < NC) out[row * NC + t] = lc - lse;
}

// ---------------- launch ----------------
extern "C" void kernel_launch(void* const* d_in, const int* in_sizes, int n_in,
                              void* d_out, int out_size) {
    const float* x       = (const float*)d_in[0];
    const float* means   = (const float*)d_in[1];
    const float* bw      = (const float*)d_in[2];
    const float* weights = (const float*)d_in[3];
    const float* priors  = (const float*)d_in[4];
    float* out = (float*)d_out;

    cudaFuncSetAttribute(gemm_kernel, cudaFuncAttributeMaxDynamicSharedMemorySize, SMEM_TOTAL);

    fused_prep_kernel<<<PREP_BLOCKS, 256>>>(x, means, bw, weights, priors);

    dim3 grid(NCK / BN, NB / BM);   // (25, 64)
    gemm_kernel<<<grid, NTHR, SMEM_TOTAL>>>();

    reduce_kernel<<<NB, 256>>>(out);
}

// round 15
// speedup vs baseline: 1.0009x; 1.0009x over previous
#include <cuda_runtime.h>
#include <cuda_bf16.h>
#include <math.h>
#include <stdint.h>

// Problem constants
#define NB   8192
#define NC   200
#define NK   16
#define ND   512
#define NCK  3200
#define K2   1024          // 2*ND concatenated GEMM K
#define D_LOG_2PI 940.9930579935848f

// GEMM tiling (champion config)
#define BM 128
#define BN 128
#define BK 32
#define NSTEPS (K2/BK)     // 32
#define NTHR 256
#define NSTAGE 3

#define STAGE_BYTES 32768
#define BIAS_OFF    (NSTAGE * STAGE_BYTES)          // bias AFTER stages
#define SMEM_TOTAL  (BIAS_OFF + 512)
#define CPAD 136

// fused prep grid partition
#define PX_BLOCKS 4096                  // NB*ND/4/256
#define PC_BLOCKS NCK                   // one component per block
#define PREP_BLOCKS (PX_BLOCKS + PC_BLOCKS + 1)

// ---------------- scratch (device globals) ----------------
__device__ __nv_bfloat16 g_Ah[NB * K2];
__device__ __nv_bfloat16 g_Al[NB * K2];
__device__ __nv_bfloat16 g_Bh[NCK * K2];
__device__ __nv_bfloat16 g_Bl[NCK * K2];
__device__ float g_bias[NCK];
__device__ float g_logp[NC];
__device__ float g_cls[NB * NC];

// ---------------- helpers ----------------
__device__ __forceinline__ uint32_t smem_u32(const void* p) {
    uint32_t a;
    asm("{ .reg .u64 t; cvta.to.shared.u64 t, %1; cvt.u32.u64 %0, t; }" : "=r"(a) : "l"(p));
    return a;
}
__device__ __forceinline__ uint32_t swz(uint32_t o) {   // SW128 over 128B rows
    return o ^ (((o >> 7) & 7) << 4);
}
__device__ __forceinline__ void cp16(uint32_t saddr, const void* gaddr) {
    asm volatile("cp.async.cg.shared.global [%0], [%1], 16;" :: "r"(saddr), "l"(gaddr));
}
__device__ __forceinline__ void ldsm4(uint32_t* r, uint32_t addr) {
    asm volatile("ldmatrix.sync.aligned.m8n8.x4.shared.b16 {%0,%1,%2,%3}, [%4];"
        : "=r"(r[0]), "=r"(r[1]), "=r"(r[2]), "=r"(r[3]) : "r"(addr));
}
__device__ __forceinline__ void mma4(float* c, const uint32_t* a, uint32_t b0, uint32_t b1) {
    asm("mma.sync.aligned.m16n8k16.row.col.f32.bf16.bf16.f32 "
        "{%0,%1,%2,%3}, {%4,%5,%6,%7}, {%8,%9}, {%0,%1,%2,%3};"
        : "+f"(c[0]), "+f"(c[1]), "+f"(c[2]), "+f"(c[3])
        : "r"(a[0]), "r"(a[1]), "r"(a[2]), "r"(a[3]), "r"(b0), "r"(b1));
}
__device__ __forceinline__ uint32_t pack2(__nv_bfloat16 a, __nv_bfloat16 b) {
    __nv_bfloat162 v(a, b);
    return *(uint32_t*)&v;
}

// ================= fused prep: x-split | comp-split+bias | priors =================
__global__ void fused_prep_kernel(const float* __restrict__ x,
                                  const float* __restrict__ means,
                                  const float* __restrict__ bw,
                                  const float* __restrict__ weights,
                                  const float* __restrict__ priors) {
    __shared__ float sh[256];
    int bid = blockIdx.x;
    int t = threadIdx.x;

    if (bid < PX_BLOCKS) {
        // ---- A' = [x^2 | x] hi/lo, 4 elems/thread, 8B packed stores ----
        int i = bid * 256 + t;          // over NB*ND/4, exact
        int b = i >> 7;
        int d4 = (i & 127) * 4;
        float4 v = *(const float4*)(x + (size_t)b * ND + d4);
        float vv[4] = {v.x, v.y, v.z, v.w};
        __nv_bfloat16 h[4], l[4], h2[4], l2[4];
        #pragma unroll
        for (int q = 0; q < 4; q++) {
            float a = vv[q] * vv[q];
            h[q] = __float2bfloat16(a);
            l[q] = __float2bfloat16(a - __bfloat162float(h[q]));
            h2[q] = __float2bfloat16(vv[q]);
            l2[q] = __float2bfloat16(vv[q] - __bfloat162float(h2[q]));
        }
        size_t base = (size_t)b * K2 + d4;
        *(uint2*)(g_Ah + base)      = make_uint2(pack2(h[0], h[1]),  pack2(h[2], h[3]));
        *(uint2*)(g_Al + base)      = make_uint2(pack2(l[0], l[1]),  pack2(l[2], l[3]));
        *(uint2*)(g_Ah + base + ND) = make_uint2(pack2(h2[0], h2[1]), pack2(h2[2], h2[3]));
        *(uint2*)(g_Al + base + ND) = make_uint2(pack2(l2[0], l2[1]), pack2(l2[2], l2[3]));

    } else if (bid < PX_BLOCKS + PC_BLOCKS) {
        // ---- B' = [invb | -2mu*invb] hi/lo + bias(j), 2 elems/thread ----
        int j = bid - PX_BLOCKS;
        int d2 = t * 2;
        float2 bv2 = *(const float2*)(bw + (size_t)j * ND + d2);
        float2 mu2 = *(const float2*)(means + (size_t)j * ND + d2);
        float bvv[2] = {bv2.x, bv2.y};
        float muv[2] = {mu2.x, mu2.y};
        float ld = 0.f, cj = 0.f;
        __nv_bfloat16 bh[2], bl[2], mh[2], ml[2];
        #pragma unroll
        for (int q = 0; q < 2; q++) {
            float bv = fminf(fmaxf(bvv[q], 1e-6f), 1000.f);
            float inv = 1.0f / bv;
            float m2  = -2.0f * muv[q] * inv;
            bh[q] = __float2bfloat16(inv);
            bl[q] = __float2bfloat16(inv - __bfloat162float(bh[q]));
            mh[q] = __float2bfloat16(m2);
            ml[q] = __float2bfloat16(m2 - __bfloat162float(mh[q]));
            ld += logf(bv);
            cj += muv[q] * muv[q] * inv;
        }
        size_t base = (size_t)j * K2 + d2;
        *(uint32_t*)(g_Bh + base)      = pack2(bh[0], bh[1]);
        *(uint32_t*)(g_Bl + base)      = pack2(bl[0], bl[1]);
        *(uint32_t*)(g_Bh + base + ND) = pack2(mh[0], mh[1]);
        *(uint32_t*)(g_Bl + base + ND) = pack2(ml[0], ml[1]);

        // reduce ld, cj over 256 threads
        #pragma unroll
        for (int o = 16; o > 0; o >>= 1) {
            ld += __shfl_down_sync(0xffffffff, ld, o);
            cj += __shfl_down_sync(0xffffffff, cj, o);
        }
        if ((t & 31) == 0) { sh[t >> 5] = ld; sh[8 + (t >> 5)] = cj; }
        __syncthreads();
        if (t == 0) {
            float LD = 0.f, CJ = 0.f;
            #pragma unroll
            for (int w = 0; w < 8; w++) { LD += sh[w]; CJ += sh[8 + w]; }
            // local class-weight softmax -> logw_j (no cross-block dependency)
            int c = j >> 4, k = j & 15;
            float wv[NK];
            float m = -1e30f;
            #pragma unroll
            for (int q = 0; q < NK; q++) { wv[q] = weights[c * NK + q]; m = fmaxf(m, wv[q]); }
            float s = 0.f;
            #pragma unroll
            for (int q = 0; q < NK; q++) s += expf(wv[q] - m);
            float logw = logf(expf(wv[k] - m) / s + 1e-6f);
            g_bias[j] = -0.5f * (D_LOG_2PI + LD + CJ) + logw;
        }

    } else {
        // ---- priors softmax -> g_logp ----
        float pv = (t < NC) ? priors[t] : -1e30f;
        sh[t] = pv;
        __syncthreads();
        for (int s = 128; s > 0; s >>= 1) { if (t < s) sh[t] = fmaxf(sh[t], sh[t + s]); __syncthreads(); }
        float M = sh[0];
        __syncthreads();
        float e = (t < NC) ? expf(pv - M) : 0.f;
        sh[t] = e;
        __syncthreads();
        for (int s = 128; s > 0; s >>= 1) { if (t < s) sh[t] += sh[t + s]; __syncthreads(); }
        float S = sh[0];
        if (t < NC) g_logp[t] = logf(e / S + 1e-6f);
    }
}

// ---------------- main GEMM (champion, bf16x3, 2 CTAs/SM) ----------------
__global__ void __launch_bounds__(NTHR, 2) gemm_kernel() {
    extern __shared__ char smem[];
    uint32_t sb = smem_u32(smem);
    int tid = threadIdx.x;
    int wid = tid >> 5, lane = tid & 31;
    int rowBase = blockIdx.y * BM;
    int colBase = blockIdx.x * BN;
    float* bias_sm = (float*)(smem + BIAS_OFF);

    if (tid < 128) bias_sm[tid] = g_bias[colBase + tid];

    int wm = (wid & 1) * 64;
    int wn = (wid >> 1) * 32;
    int lrow = lane & 15;
    uint32_t lcol = (uint32_t)((lane >> 4) * 16);

    const __nv_bfloat16* pA[4]; uint32_t sA[4];
    const __nv_bfloat16* pB[4]; uint32_t sB[4];
    #pragma unroll
    for (int it = 0; it < 4; it++) {
        int idx = tid + it * NTHR;
        int row = idx >> 3, ch = idx & 7;
        uint32_t goff = (uint32_t)((rowBase + row) * K2 + (ch & 3) * 8);
        pA[it] = (ch < 4 ? g_Ah : g_Al) + goff;
        sA[it] = swz((uint32_t)(row * 128 + ch * 16));
        uint32_t goffB = (uint32_t)((colBase + row) * K2 + (ch & 3) * 8);
        pB[it] = (ch < 4 ? g_Bh : g_Bl) + goffB;
        sB[it] = swz((uint32_t)(row * 128 + ch * 16));
    }

    uint32_t baseA[4], baseB[2];
    #pragma unroll
    for (int mi = 0; mi < 4; mi++) {
        int r = wm + mi * 16 + lrow;
        baseA[mi] = sb + (uint32_t)(r * 128 + ((r & 7) << 4));
    }
    #pragma unroll
    for (int nj = 0; nj < 2; nj++) {
        int r = wn + nj * 16 + lrow;
        baseB[nj] = sb + 16384 + (uint32_t)(r * 128 + ((r & 7) << 4));
    }

    float acc[64];
    #pragma unroll
    for (int i = 0; i < 64; i++) acc[i] = 0.f;

    auto load_stage = [&](int st) {
        uint32_t sa = sb + (uint32_t)st * STAGE_BYTES;
        #pragma unroll
        for (int it = 0; it < 4; it++) {
            cp16(sa + sA[it],          pA[it]);
            cp16(sa + 16384 + sB[it],  pB[it]);
            pA[it] += BK;
            pB[it] += BK;
        }
        asm volatile("cp.async.commit_group;" ::: "memory");
    };

    load_stage(0);
    load_stage(1);

    int st = 0;
    for (int s = 0; s < NSTEPS; s++) {
        if (s < NSTEPS - 2)
            asm volatile("cp.async.wait_group 1;" ::: "memory");
        else
            asm volatile("cp.async.wait_group 0;" ::: "memory");
        __syncthreads();

        uint32_t so = (uint32_t)st * STAGE_BYTES;

        if (s + 2 < NSTEPS) {
            int nst = st + 2; if (nst >= NSTAGE) nst -= NSTAGE;
            load_stage(nst);
        }

        #pragma unroll
        for (int ks = 0; ks < 2; ks++) {
            uint32_t kb = (uint32_t)(ks * 32) + lcol;
            uint32_t kl = kb + 64u;

            uint32_t bh0[4], bh1[4], bl0[4], bl1[4];
            ldsm4(bh0, (baseB[0] + so) ^ kb);
            ldsm4(bh1, (baseB[1] + so) ^ kb);
            ldsm4(bl0, (baseB[0] + so) ^ kl);
            ldsm4(bl1, (baseB[1] + so) ^ kl);

            #pragma unroll
            for (int mi = 0; mi < 4; mi++) {
                float* C = &acc[mi * 16];
                uint32_t ah[4], al[4];
                ldsm4(ah, (baseA[mi] + so) ^ kb);
                mma4(C + 0,  ah, bh0[0], bh0[2]);
                mma4(C + 4,  ah, bh0[1], bh0[3]);
                mma4(C + 8,  ah, bh1[0], bh1[2]);
                mma4(C + 12, ah, bh1[1], bh1[3]);
                ldsm4(al, (baseA[mi] + so) ^ kl);
                mma4(C + 0,  ah, bl0[0], bl0[2]);
                mma4(C + 4,  ah, bl0[1], bl0[3]);
                mma4(C + 8,  ah, bl1[0], bl1[2]);
                mma4(C + 12, ah, bl1[1], bl1[3]);
                mma4(C + 0,  al, bh0[0], bh0[2]);
                mma4(C + 4,  al, bh0[1], bh0[3]);
                mma4(C + 8,  al, bh1[0], bh1[2]);
                mma4(C + 12, al, bh1[1], bh1[3]);
            }
        }
        st++; if (st >= NSTAGE) st = 0;
    }
    __syncthreads();

    // ---- epilogue: stage C to smem (offset 0; bias untouched), fused lse ----
    float* csh = (float*)smem;
    #pragma unroll
    for (int mi = 0; mi < 4; mi++)
        #pragma unroll
        for (int nj = 0; nj < 4; nj++) {
            float* a = &acc[(mi * 4 + nj) * 4];
            int r0 = wm + mi * 16 + (lane >> 2);
            int c0 = wn + nj * 8 + 2 * (lane & 3);
            csh[r0 * CPAD + c0]           = a[0];
            csh[r0 * CPAD + c0 + 1]       = a[1];
            csh[(r0 + 8) * CPAD + c0]     = a[2];
            csh[(r0 + 8) * CPAD + c0 + 1] = a[3];
        }
    __syncthreads();

    #pragma unroll
    for (int i = 0; i < 4; i++) {
        int p = tid + i * NTHR;
        int row = p >> 3, cl = p & 7;
        const float* base = &csh[row * CPAD + cl * 16];
        float4 x0 = *(const float4*)(base + 0);
        float4 x1 = *(const float4*)(base + 4);
        float4 x2 = *(const float4*)(base + 8);
        float4 x3 = *(const float4*)(base + 12);
        float v[16] = {x0.x, x0.y, x0.z, x0.w, x1.x, x1.y, x1.z, x1.w,
                       x2.x, x2.y, x2.z, x2.w, x3.x, x3.y, x3.z, x3.w};
        #pragma unroll
        for (int j = 0; j < 16; j++)
            v[j] = fmaf(-0.5f, v[j], bias_sm[cl * 16 + j]);
        float m = v[0];
        #pragma unroll
        for (int j = 1; j < 16; j++) m = fmaxf(m, v[j]);
        float sum = 0.f;
        #pragma unroll
        for (int j = 0; j < 16; j++) sum += __expf(v[j] - m);
        g_cls[(size_t)(rowBase + row) * NC + (colBase >> 4) + cl] = m + __logf(sum);
    }
}

// ---------------- per-row reduction over classes ----------------
__global__ void reduce_kernel(float* __restrict__ out) {
    __shared__ float sh[256];
    size_t row = blockIdx.x;
    int t = threadIdx.x;
    float lc = -1e30f;
    if (t < NC) lc = g_cls[row * NC + t] + g_logp[t];
    sh[t] = lc;
    __syncthreads();
    for (int s = 128; s > 0; s >>= 1) { if (t < s) sh[t] = fmaxf(sh[t], sh[t + s]); __syncthreads(); }
    float M = sh[0];
    __syncthreads();
    sh[t] = (t < NC) ? __expf(lc - M) : 0.f;
    __syncthreads();
    for (int s = 128; s > 0; s >>= 1) { if (t < s) sh[t] += sh[t + s]; __syncthreads(); }
    float lse = M + __logf(sh[0]);
    if (t < NC) out[row * NC + t] = lc - lse;
}

// ---------------- launch ----------------
extern "C" void kernel_launch(void* const* d_in, const int* in_sizes, int n_in,
                              void* d_out, int out_size) {
    const float* x       = (const float*)d_in[0];
    const float* means   = (const float*)d_in[1];
    const float* bw      = (const float*)d_in[2];
    const float* weights = (const float*)d_in[3];
    const float* priors  = (const float*)d_in[4];
    float* out = (float*)d_out;

    cudaFuncSetAttribute(gemm_kernel, cudaFuncAttributeMaxDynamicSharedMemorySize, SMEM_TOTAL);

    fused_prep_kernel<<<PREP_BLOCKS, 256>>>(x, means, bw, weights, priors);

    dim3 grid(NCK / BN, NB / BM);   // (25, 64)
    gemm_kernel<<<grid, NTHR, SMEM_TOTAL>>>();

    reduce_kernel<<<NB, 256>>>(out);
}